// round 14
// baseline (speedup 1.0000x reference)
#include <cuda_runtime.h>
#include <cstdint>
#include <math_constants.h>

constexpr int C  = 128;
constexpr int KN = 16;
constexpr int NMAX = 100000;

// ---------------- device scratch -------------------------------------------
__device__ float g_h0[(size_t)NMAX * C];
__device__ float g_pooled[(size_t)NMAX * C];
__device__ float g_t[(size_t)NMAX * C];
__device__ float g_u[(size_t)NMAX * C];

__device__ float g_sum[4][C];
__device__ float g_sq[4][C];

// ---------------- helpers ----------------------------------------------------
__device__ __forceinline__ uint32_t f2tf32(float x) {
    uint32_t r;
    asm("cvt.rna.tf32.f32 %0, %1;" : "=r"(r) : "f"(x));
    return r;
}

__device__ __forceinline__ void mma_tf32(float* d, const uint32_t* a,
                                         uint32_t b0, uint32_t b1) {
    asm volatile(
        "mma.sync.aligned.m16n8k8.row.col.f32.tf32.tf32.f32 "
        "{%0,%1,%2,%3}, {%4,%5,%6,%7}, {%8,%9}, {%0,%1,%2,%3};"
        : "+f"(d[0]), "+f"(d[1]), "+f"(d[2]), "+f"(d[3])
        : "r"(a[0]), "r"(a[1]), "r"(a[2]), "r"(a[3]), "r"(b0), "r"(b1));
}

__device__ __forceinline__ void bn_coeff(int s, int c, const float* gamma,
                                         const float* beta, float invN,
                                         float& sc, float& sh) {
    float mean = g_sum[s][c] * invN;
    float var  = g_sq[s][c] * invN - mean * mean;
    sc = __ldg(gamma + c) * rsqrtf(var + 1e-5f);
    sh = __ldg(beta + c) - mean * sc;
}

// ---------------- tiny kernels ----------------------------------------------
__global__ void zero_stats_kernel() {
    int i = threadIdx.x;
    if (i < C) {
        #pragma unroll
        for (int s = 0; s < 4; s++) { g_sum[s][i] = 0.f; g_sq[s][i] = 0.f; }
    }
}

// ---------------- tf32 GEMM v6: R11 core, 512 threads (16 warps x 16 rows) ---
constexpr int PADW = 136;
constexpr int BM   = 256;

template <int MODE>
__global__ __launch_bounds__(512, 1)
void gemm_kernel(const float* __restrict__ A,
                 const float* __restrict__ W,
                 const float* __restrict__ bias,
                 float* __restrict__ out,
                 const float* __restrict__ gamma,
                 const float* __restrict__ beta,
                 float invN,
                 int stat_in, int stat_out, int N) {
    extern __shared__ float smem[];
    uint32_t* sW     = (uint32_t*)smem;            // [128][136] tf32 bits
    uint32_t* sA     = sW + 128 * PADW;            // [256][136] tf32 bits
    float*    sSum   = (float*)(sA + BM * PADW);
    float*    sSq    = sSum + C;
    float*    sScale = sSq + C;
    float*    sShift = sScale + C;

    const int tid  = threadIdx.x;
    const int row0 = blockIdx.x * BM;

    if (tid < C) {
        sSum[tid] = 0.f; sSq[tid] = 0.f;
        if (MODE >= 1) {
            float sc, sh;
            bn_coeff(stat_in, tid, gamma, beta, invN, sc, sh);
            sScale[tid] = sc; sShift[tid] = sh;
        }
    }
    if (MODE >= 1) __syncthreads();

    // stage W (tf32)
    for (int i = tid * 4; i < C * C; i += 2048) {
        int k = i >> 7, n = i & 127;
        float4 w = *(const float4*)(W + i);
        uint4 t4;
        t4.x = f2tf32(w.x); t4.y = f2tf32(w.y);
        t4.z = f2tf32(w.z); t4.w = f2tf32(w.w);
        *(uint4*)(sW + k * PADW + n) = t4;
    }
    // stage A' (BN transform + tf32)
    for (int i = tid * 4; i < BM * C; i += 2048) {
        int r = i >> 7, c = i & 127;
        int row = row0 + r;
        float4 v = make_float4(0.f, 0.f, 0.f, 0.f);
        if (row < N) v = *(const float4*)(A + (size_t)row * C + c);
        if (MODE >= 1) {
            v.x = fmaf(v.x, sScale[c + 0], sShift[c + 0]);
            v.y = fmaf(v.y, sScale[c + 1], sShift[c + 1]);
            v.z = fmaf(v.z, sScale[c + 2], sShift[c + 2]);
            v.w = fmaf(v.w, sScale[c + 3], sShift[c + 3]);
            if (MODE == 2) {
                v.x = fmaxf(v.x, 0.f); v.y = fmaxf(v.y, 0.f);
                v.z = fmaxf(v.z, 0.f); v.w = fmaxf(v.w, 0.f);
            }
        }
        uint4 t4;
        t4.x = f2tf32(v.x); t4.y = f2tf32(v.y);
        t4.z = f2tf32(v.z); t4.w = f2tf32(v.w);
        *(uint4*)(sA + r * PADW + c) = t4;
    }
    __syncthreads();

    const int warp = tid >> 5, lane = tid & 31;
    const int g = lane >> 2, t = lane & 3;
    const int r0w = warp * 16;

    float d[16][4];
    #pragma unroll
    for (int nf = 0; nf < 16; nf++)
        #pragma unroll
        for (int j = 0; j < 4; j++) d[nf][j] = 0.f;

    #pragma unroll 1
    for (int ks = 0; ks < 16; ks++) {
        const int k0 = ks * 8;
        uint32_t a[4];
        const uint32_t* p = sA + (r0w + g) * PADW + k0 + t;
        a[0] = p[0];
        a[1] = p[8 * PADW];
        a[2] = p[4];
        a[3] = p[8 * PADW + 4];
        const uint32_t* bp = sW + (k0 + t) * PADW + g;
        #pragma unroll
        for (int nf = 0; nf < 16; nf++) {
            uint32_t b0 = bp[nf * 8];
            uint32_t b1 = bp[4 * PADW + nf * 8];
            mma_tf32(d[nf], a, b0, b1);
        }
    }

    // epilogue: bias + direct stores + shfl-reduced stats
    const int rowT = row0 + r0w + g;
    const int rowB = rowT + 8;
    const bool vT = (rowT < N), vB = (rowB < N);
    float* outT = out + (size_t)rowT * C;
    float* outB = out + (size_t)rowB * C;

    #pragma unroll
    for (int nf = 0; nf < 16; nf++) {
        const int c0 = nf * 8 + 2 * t;
        const float b0 = __ldg(bias + c0), b1 = __ldg(bias + c0 + 1);
        float x0 = d[nf][0] + b0, y0 = d[nf][1] + b1;   // row T
        float x1 = d[nf][2] + b0, y1 = d[nf][3] + b1;   // row B
        float s0 = 0.f, s1 = 0.f, q0 = 0.f, q1 = 0.f;
        if (vT) {
            *(float2*)(outT + c0) = make_float2(x0, y0);
            s0 += x0; s1 += y0; q0 += x0 * x0; q1 += y0 * y0;
        }
        if (vB) {
            *(float2*)(outB + c0) = make_float2(x1, y1);
            s0 += x1; s1 += y1; q0 += x1 * x1; q1 += y1 * y1;
        }
        #pragma unroll
        for (int off = 4; off < 32; off <<= 1) {
            s0 += __shfl_xor_sync(0xffffffffu, s0, off);
            s1 += __shfl_xor_sync(0xffffffffu, s1, off);
            q0 += __shfl_xor_sync(0xffffffffu, q0, off);
            q1 += __shfl_xor_sync(0xffffffffu, q1, off);
        }
        if (lane < 4) {
            atomicAdd(&sSum[c0], s0);     atomicAdd(&sSum[c0 + 1], s1);
            atomicAdd(&sSq[c0], q0);      atomicAdd(&sSq[c0 + 1], q1);
        }
    }
    __syncthreads();
    if (tid < C) {
        atomicAdd(&g_sum[stat_out][tid], sSum[tid]);
        atomicAdd(&g_sq[stat_out][tid],  sSq[tid]);
    }
}

// ---------------- gather + max-pool (R11 verbatim) ---------------------------
__global__ __launch_bounds__(256)
void gather_kernel(const float* __restrict__ pe,
                   const int* __restrict__ knn,
                   float* __restrict__ pooled,
                   const float* __restrict__ gamma,
                   const float* __restrict__ beta,
                   float invN, int N) {
    const int w    = (blockIdx.x * blockDim.x + threadIdx.x) >> 5;
    const int lane = threadIdx.x & 31;
    const int kg   = lane >> 3;
    const int cg   = lane & 7;
    const int c4   = (w & 3) * 32 + cg * 4;
    const int nG   = (gridDim.x * blockDim.x) >> 7;

    float4 sc, sh;
    bn_coeff(0, c4 + 0, gamma, beta, invN, sc.x, sh.x);
    bn_coeff(0, c4 + 1, gamma, beta, invN, sc.y, sh.y);
    bn_coeff(0, c4 + 2, gamma, beta, invN, sc.z, sh.z);
    bn_coeff(0, c4 + 3, gamma, beta, invN, sc.w, sh.w);

    float4 lsum = make_float4(0.f, 0.f, 0.f, 0.f);
    float4 lsq  = make_float4(0.f, 0.f, 0.f, 0.f);

    for (int n = (w >> 2); n < N; n += 2 * nG) {
        const int  n2 = n + nG;
        const bool v2 = (n2 < N);
        const int  n2c = v2 ? n2 : n;

        int4 iA = __ldg((const int4*)(knn + (size_t)n  * KN) + kg);
        int4 iB = __ldg((const int4*)(knn + (size_t)n2c * KN) + kg);

        const float4* peA =
            (const float4*)(pe + (((size_t)n * KN + kg * 4) << 7) + c4);
        const float4* peB =
            (const float4*)(pe + (((size_t)n2c * KN + kg * 4) << 7) + c4);

        float4 pa0 = __ldcs(peA),      pa1 = __ldcs(peA + 32);
        float4 pa2 = __ldcs(peA + 64), pa3 = __ldcs(peA + 96);
        float4 pb0 = __ldcs(peB),      pb1 = __ldcs(peB + 32);
        float4 pb2 = __ldcs(peB + 64), pb3 = __ldcs(peB + 96);

        float4 ha0 = __ldg((const float4*)(g_h0 + (((size_t)iA.x) << 7) + c4));
        float4 ha1 = __ldg((const float4*)(g_h0 + (((size_t)iA.y) << 7) + c4));
        float4 ha2 = __ldg((const float4*)(g_h0 + (((size_t)iA.z) << 7) + c4));
        float4 ha3 = __ldg((const float4*)(g_h0 + (((size_t)iA.w) << 7) + c4));
        float4 hb0 = __ldg((const float4*)(g_h0 + (((size_t)iB.x) << 7) + c4));
        float4 hb1 = __ldg((const float4*)(g_h0 + (((size_t)iB.y) << 7) + c4));
        float4 hb2 = __ldg((const float4*)(g_h0 + (((size_t)iB.z) << 7) + c4));
        float4 hb3 = __ldg((const float4*)(g_h0 + (((size_t)iB.w) << 7) + c4));

        float4 mA = make_float4(-CUDART_INF_F, -CUDART_INF_F,
                                -CUDART_INF_F, -CUDART_INF_F);
        float4 mB = mA;

        #define GMAX(m, pv, hv)                                           \
        {                                                                 \
            float4 h = hv;                                                \
            h.x = fmaxf(fmaf(h.x, sc.x, sh.x), 0.f);                      \
            h.y = fmaxf(fmaf(h.y, sc.y, sh.y), 0.f);                      \
            h.z = fmaxf(fmaf(h.z, sc.z, sh.z), 0.f);                      \
            h.w = fmaxf(fmaf(h.w, sc.w, sh.w), 0.f);                      \
            m.x = fmaxf(m.x, pv.x + h.x);                                 \
            m.y = fmaxf(m.y, pv.y + h.y);                                 \
            m.z = fmaxf(m.z, pv.z + h.z);                                 \
            m.w = fmaxf(m.w, pv.w + h.w);                                 \
        }
        GMAX(mA, pa0, ha0) GMAX(mA, pa1, ha1)
        GMAX(mA, pa2, ha2) GMAX(mA, pa3, ha3)
        GMAX(mB, pb0, hb0) GMAX(mB, pb1, hb1)
        GMAX(mB, pb2, hb2) GMAX(mB, pb3, hb3)
        #undef GMAX

        #define WRED(m)                                                    \
        m.x = fmaxf(m.x, __shfl_xor_sync(0xffffffffu, m.x, 8));            \
        m.y = fmaxf(m.y, __shfl_xor_sync(0xffffffffu, m.y, 8));            \
        m.z = fmaxf(m.z, __shfl_xor_sync(0xffffffffu, m.z, 8));            \
        m.w = fmaxf(m.w, __shfl_xor_sync(0xffffffffu, m.w, 8));            \
        m.x = fmaxf(m.x, __shfl_xor_sync(0xffffffffu, m.x, 16));           \
        m.y = fmaxf(m.y, __shfl_xor_sync(0xffffffffu, m.y, 16));           \
        m.z = fmaxf(m.z, __shfl_xor_sync(0xffffffffu, m.z, 16));           \
        m.w = fmaxf(m.w, __shfl_xor_sync(0xffffffffu, m.w, 16));
        WRED(mA)
        WRED(mB)
        #undef WRED

        if (kg == 0) {
            *(float4*)(pooled + (((size_t)n) << 7) + c4) = mA;
            lsum.x += mA.x; lsum.y += mA.y; lsum.z += mA.z; lsum.w += mA.w;
            lsq.x += mA.x * mA.x; lsq.y += mA.y * mA.y;
            lsq.z += mA.z * mA.z; lsq.w += mA.w * mA.w;
            if (v2) {
                *(float4*)(pooled + (((size_t)n2) << 7) + c4) = mB;
                lsum.x += mB.x; lsum.y += mB.y; lsum.z += mB.z; lsum.w += mB.w;
                lsq.x += mB.x * mB.x; lsq.y += mB.y * mB.y;
                lsq.z += mB.z * mB.z; lsq.w += mB.w * mB.w;
            }
        }
    }

    if (kg == 0) {
        atomicAdd(&g_sum[1][c4 + 0], lsum.x); atomicAdd(&g_sum[1][c4 + 1], lsum.y);
        atomicAdd(&g_sum[1][c4 + 2], lsum.z); atomicAdd(&g_sum[1][c4 + 3], lsum.w);
        atomicAdd(&g_sq[1][c4 + 0], lsq.x);   atomicAdd(&g_sq[1][c4 + 1], lsq.y);
        atomicAdd(&g_sq[1][c4 + 2], lsq.z);   atomicAdd(&g_sq[1][c4 + 3], lsq.w);
    }
}

// ---------------- residual epilogue (inline bn4) ------------------------------
__global__ void final_kernel(const float* __restrict__ f,
                             float* __restrict__ out,
                             const float* __restrict__ gamma,
                             const float* __restrict__ beta,
                             float invN, int N) {
    int i = (blockIdx.x * blockDim.x + threadIdx.x) * 4;
    if (i >= N * C) return;
    int c = i & (C - 1);
    float4 sc, sh;
    bn_coeff(3, c + 0, gamma, beta, invN, sc.x, sh.x);
    bn_coeff(3, c + 1, gamma, beta, invN, sc.y, sh.y);
    bn_coeff(3, c + 2, gamma, beta, invN, sc.z, sh.z);
    bn_coeff(3, c + 3, gamma, beta, invN, sc.w, sh.w);
    float4 fv = *(const float4*)(f + i);
    float4 uv = *(const float4*)(g_u + i);
    float4 o;
    o.x = fmaxf(fv.x + fmaf(uv.x, sc.x, sh.x), 0.f);
    o.y = fmaxf(fv.y + fmaf(uv.y, sc.y, sh.y), 0.f);
    o.z = fmaxf(fv.z + fmaf(uv.z, sc.z, sh.z), 0.f);
    o.w = fmaxf(fv.w + fmaf(uv.w, sc.w, sh.w), 0.f);
    *(float4*)(out + i) = o;
}

// ---------------- launcher ----------------------------------------------------
extern "C" void kernel_launch(void* const* d_in, const int* in_sizes, int n_in,
                              void* d_out, int out_size) {
    const float* f_in  = (const float*)d_in[1];
    const float* pe    = (const float*)d_in[2];
    const int*   knn   = (const int*)  d_in[3];
    const float* W_pre = (const float*)d_in[4];
    const float* b_pre = (const float*)d_in[5];
    const float* g1    = (const float*)d_in[6];
    const float* be1   = (const float*)d_in[7];
    const float* g2    = (const float*)d_in[8];
    const float* be2   = (const float*)d_in[9];
    const float* W_f1  = (const float*)d_in[10];
    const float* b_f1  = (const float*)d_in[11];
    const float* g3    = (const float*)d_in[12];
    const float* be3   = (const float*)d_in[13];
    const float* W_f2  = (const float*)d_in[14];
    const float* b_f2  = (const float*)d_in[15];
    const float* g4    = (const float*)d_in[16];
    const float* be4   = (const float*)d_in[17];
    float* out = (float*)d_out;

    const int N = in_sizes[0] / 3;
    const float invN = 1.0f / (float)N;

    float *p_h0, *p_pooled, *p_t, *p_u;
    cudaGetSymbolAddress((void**)&p_h0, g_h0);
    cudaGetSymbolAddress((void**)&p_pooled, g_pooled);
    cudaGetSymbolAddress((void**)&p_t, g_t);
    cudaGetSymbolAddress((void**)&p_u, g_u);

    const int SMEM_GEMM =
        (128 * PADW + BM * PADW + 4 * C) * (int)sizeof(float);   // ~211 KB
    cudaFuncSetAttribute(gemm_kernel<0>, cudaFuncAttributeMaxDynamicSharedMemorySize, SMEM_GEMM);
    cudaFuncSetAttribute(gemm_kernel<1>, cudaFuncAttributeMaxDynamicSharedMemorySize, SMEM_GEMM);
    cudaFuncSetAttribute(gemm_kernel<2>, cudaFuncAttributeMaxDynamicSharedMemorySize, SMEM_GEMM);

    const int gemmGrid   = (N + BM - 1) / BM;
    const int gatherGrid = 1184;
    const int finalGrid  = (N * C / 4 + 255) / 256;

    zero_stats_kernel<<<1, 128>>>();

    gemm_kernel<0><<<gemmGrid, 512, SMEM_GEMM>>>(
        f_in, W_pre, b_pre, p_h0, nullptr, nullptr, invN, 0, 0, N);

    gather_kernel<<<gatherGrid, 256>>>(pe, knn, p_pooled, g1, be1, invN, N);

    gemm_kernel<1><<<gemmGrid, 512, SMEM_GEMM>>>(
        p_pooled, W_f1, b_f1, p_t, g2, be2, invN, 1, 2, N);

    gemm_kernel<2><<<gemmGrid, 512, SMEM_GEMM>>>(
        p_t, W_f2, b_f2, p_u, g3, be3, invN, 2, 3, N);

    final_kernel<<<finalGrid, 256>>>(f_in, out, g4, be4, invN, N);
}

// round 15
// speedup vs baseline: 1.0225x; 1.0225x over previous
#include <cuda_runtime.h>
#include <cstdint>
#include <math_constants.h>

constexpr int C  = 128;
constexpr int KN = 16;
constexpr int NMAX = 100000;

// ---------------- device scratch -------------------------------------------
__device__ float g_h0[(size_t)NMAX * C];
__device__ float g_pooled[(size_t)NMAX * C];
__device__ float g_t[(size_t)NMAX * C];
__device__ float g_u[(size_t)NMAX * C];

__device__ float g_sum[4][C];
__device__ float g_sq[4][C];

// ---------------- helpers ----------------------------------------------------
__device__ __forceinline__ uint32_t f2tf32(float x) {
    uint32_t r;
    asm("cvt.rna.tf32.f32 %0, %1;" : "=r"(r) : "f"(x));
    return r;
}

__device__ __forceinline__ void mma_tf32(float* d, const uint32_t* a,
                                         uint32_t b0, uint32_t b1) {
    asm volatile(
        "mma.sync.aligned.m16n8k8.row.col.f32.tf32.tf32.f32 "
        "{%0,%1,%2,%3}, {%4,%5,%6,%7}, {%8,%9}, {%0,%1,%2,%3};"
        : "+f"(d[0]), "+f"(d[1]), "+f"(d[2]), "+f"(d[3])
        : "r"(a[0]), "r"(a[1]), "r"(a[2]), "r"(a[3]), "r"(b0), "r"(b1));
}

__device__ __forceinline__ void bn_coeff(int s, int c, const float* gamma,
                                         const float* beta, float invN,
                                         float& sc, float& sh) {
    float mean = g_sum[s][c] * invN;
    float var  = g_sq[s][c] * invN - mean * mean;
    sc = __ldg(gamma + c) * rsqrtf(var + 1e-5f);
    sh = __ldg(beta + c) - mean * sc;
}

// ---------------- tiny kernels ----------------------------------------------
__global__ void zero_stats_kernel() {
    int i = threadIdx.x;
    if (i < C) {
        #pragma unroll
        for (int s = 0; s < 4; s++) { g_sum[s][i] = 0.f; g_sq[s][i] = 0.f; }
    }
}

// ---------------- tf32 GEMM: R11 core + direct-store epilogue ----------------
constexpr int PADW = 136;
constexpr int BM   = 256;

template <int MODE>
__global__ __launch_bounds__(256, 1)
void gemm_kernel(const float* __restrict__ A,
                 const float* __restrict__ W,
                 const float* __restrict__ bias,
                 float* __restrict__ out,
                 const float* __restrict__ gamma,
                 const float* __restrict__ beta,
                 float invN,
                 int stat_in, int stat_out, int N) {
    extern __shared__ float smem[];
    uint32_t* sW     = (uint32_t*)smem;            // [128][136] tf32 bits
    uint32_t* sA     = sW + 128 * PADW;            // [256][136] tf32 bits
    float*    sSum   = (float*)(sA + BM * PADW);
    float*    sSq    = sSum + C;
    float*    sScale = sSq + C;
    float*    sShift = sScale + C;

    const int tid  = threadIdx.x;
    const int row0 = blockIdx.x * BM;

    if (tid < C) {
        sSum[tid] = 0.f; sSq[tid] = 0.f;
        if (MODE >= 1) {
            float sc, sh;
            bn_coeff(stat_in, tid, gamma, beta, invN, sc, sh);
            sScale[tid] = sc; sShift[tid] = sh;
        }
    }
    if (MODE >= 1) __syncthreads();

    // stage W (tf32)
    for (int i = tid * 4; i < C * C; i += 1024) {
        int k = i >> 7, n = i & 127;
        float4 w = *(const float4*)(W + i);
        uint4 t4;
        t4.x = f2tf32(w.x); t4.y = f2tf32(w.y);
        t4.z = f2tf32(w.z); t4.w = f2tf32(w.w);
        *(uint4*)(sW + k * PADW + n) = t4;
    }
    // stage A' (BN transform + tf32)
    for (int i = tid * 4; i < BM * C; i += 1024) {
        int r = i >> 7, c = i & 127;
        int row = row0 + r;
        float4 v = make_float4(0.f, 0.f, 0.f, 0.f);
        if (row < N) v = *(const float4*)(A + (size_t)row * C + c);
        if (MODE >= 1) {
            v.x = fmaf(v.x, sScale[c + 0], sShift[c + 0]);
            v.y = fmaf(v.y, sScale[c + 1], sShift[c + 1]);
            v.z = fmaf(v.z, sScale[c + 2], sShift[c + 2]);
            v.w = fmaf(v.w, sScale[c + 3], sShift[c + 3]);
            if (MODE == 2) {
                v.x = fmaxf(v.x, 0.f); v.y = fmaxf(v.y, 0.f);
                v.z = fmaxf(v.z, 0.f); v.w = fmaxf(v.w, 0.f);
            }
        }
        uint4 t4;
        t4.x = f2tf32(v.x); t4.y = f2tf32(v.y);
        t4.z = f2tf32(v.z); t4.w = f2tf32(v.w);
        *(uint4*)(sA + r * PADW + c) = t4;
    }
    __syncthreads();

    const int warp = tid >> 5, lane = tid & 31;
    const int g = lane >> 2, t = lane & 3;
    const int r0w = warp * 32;

    float d[2][16][4];
    #pragma unroll
    for (int rs = 0; rs < 2; rs++)
        #pragma unroll
        for (int nf = 0; nf < 16; nf++)
            #pragma unroll
            for (int j = 0; j < 4; j++) d[rs][nf][j] = 0.f;

    #pragma unroll 1
    for (int ks = 0; ks < 16; ks++) {
        const int k0 = ks * 8;
        uint32_t a[2][4];
        #pragma unroll
        for (int rs = 0; rs < 2; rs++) {
            const uint32_t* p = sA + (r0w + rs * 16 + g) * PADW + k0 + t;
            a[rs][0] = p[0];
            a[rs][1] = p[8 * PADW];
            a[rs][2] = p[4];
            a[rs][3] = p[8 * PADW + 4];
        }
        const uint32_t* bp = sW + (k0 + t) * PADW + g;
        #pragma unroll
        for (int nf = 0; nf < 16; nf++) {
            uint32_t b0 = bp[nf * 8];
            uint32_t b1 = bp[4 * PADW + nf * 8];
            mma_tf32(d[0][nf], a[0], b0, b1);
            mma_tf32(d[1][nf], a[1], b0, b1);
        }
    }

    // epilogue: bias + direct stores from accumulators + shfl-reduced stats
    #pragma unroll
    for (int nf = 0; nf < 16; nf++) {
        const int c0 = nf * 8 + 2 * t;
        const float b0 = __ldg(bias + c0), b1 = __ldg(bias + c0 + 1);
        float s0 = 0.f, s1 = 0.f, q0 = 0.f, q1 = 0.f;
        #pragma unroll
        for (int rs = 0; rs < 2; rs++) {
            const int rowT = row0 + r0w + rs * 16 + g;
            const int rowB = rowT + 8;
            float x0 = d[rs][nf][0] + b0, y0 = d[rs][nf][1] + b1;
            float x1 = d[rs][nf][2] + b0, y1 = d[rs][nf][3] + b1;
            if (rowT < N) {
                *(float2*)(out + (size_t)rowT * C + c0) = make_float2(x0, y0);
                s0 += x0; s1 += y0; q0 += x0 * x0; q1 += y0 * y0;
            }
            if (rowB < N) {
                *(float2*)(out + (size_t)rowB * C + c0) = make_float2(x1, y1);
                s0 += x1; s1 += y1; q0 += x1 * x1; q1 += y1 * y1;
            }
        }
        // reduce over lane bits 2..4 (the g groups sharing this column pair)
        #pragma unroll
        for (int off = 4; off < 32; off <<= 1) {
            s0 += __shfl_xor_sync(0xffffffffu, s0, off);
            s1 += __shfl_xor_sync(0xffffffffu, s1, off);
            q0 += __shfl_xor_sync(0xffffffffu, q0, off);
            q1 += __shfl_xor_sync(0xffffffffu, q1, off);
        }
        if (lane < 4) {
            atomicAdd(&sSum[c0], s0);     atomicAdd(&sSum[c0 + 1], s1);
            atomicAdd(&sSq[c0], q0);      atomicAdd(&sSq[c0 + 1], q1);
        }
    }
    __syncthreads();
    if (tid < C) {
        atomicAdd(&g_sum[stat_out][tid], sSum[tid]);
        atomicAdd(&g_sq[stat_out][tid],  sSq[tid]);
    }
}

// ---------------- gather + max-pool (R11 verbatim) ---------------------------
__global__ __launch_bounds__(256)
void gather_kernel(const float* __restrict__ pe,
                   const int* __restrict__ knn,
                   float* __restrict__ pooled,
                   const float* __restrict__ gamma,
                   const float* __restrict__ beta,
                   float invN, int N) {
    const int w    = (blockIdx.x * blockDim.x + threadIdx.x) >> 5;
    const int lane = threadIdx.x & 31;
    const int kg   = lane >> 3;
    const int cg   = lane & 7;
    const int c4   = (w & 3) * 32 + cg * 4;
    const int nG   = (gridDim.x * blockDim.x) >> 7;

    float4 sc, sh;
    bn_coeff(0, c4 + 0, gamma, beta, invN, sc.x, sh.x);
    bn_coeff(0, c4 + 1, gamma, beta, invN, sc.y, sh.y);
    bn_coeff(0, c4 + 2, gamma, beta, invN, sc.z, sh.z);
    bn_coeff(0, c4 + 3, gamma, beta, invN, sc.w, sh.w);

    float4 lsum = make_float4(0.f, 0.f, 0.f, 0.f);
    float4 lsq  = make_float4(0.f, 0.f, 0.f, 0.f);

    for (int n = (w >> 2); n < N; n += 2 * nG) {
        const int  n2 = n + nG;
        const bool v2 = (n2 < N);
        const int  n2c = v2 ? n2 : n;

        int4 iA = __ldg((const int4*)(knn + (size_t)n  * KN) + kg);
        int4 iB = __ldg((const int4*)(knn + (size_t)n2c * KN) + kg);

        const float4* peA =
            (const float4*)(pe + (((size_t)n * KN + kg * 4) << 7) + c4);
        const float4* peB =
            (const float4*)(pe + (((size_t)n2c * KN + kg * 4) << 7) + c4);

        float4 pa0 = __ldcs(peA),      pa1 = __ldcs(peA + 32);
        float4 pa2 = __ldcs(peA + 64), pa3 = __ldcs(peA + 96);
        float4 pb0 = __ldcs(peB),      pb1 = __ldcs(peB + 32);
        float4 pb2 = __ldcs(peB + 64), pb3 = __ldcs(peB + 96);

        float4 ha0 = __ldg((const float4*)(g_h0 + (((size_t)iA.x) << 7) + c4));
        float4 ha1 = __ldg((const float4*)(g_h0 + (((size_t)iA.y) << 7) + c4));
        float4 ha2 = __ldg((const float4*)(g_h0 + (((size_t)iA.z) << 7) + c4));
        float4 ha3 = __ldg((const float4*)(g_h0 + (((size_t)iA.w) << 7) + c4));
        float4 hb0 = __ldg((const float4*)(g_h0 + (((size_t)iB.x) << 7) + c4));
        float4 hb1 = __ldg((const float4*)(g_h0 + (((size_t)iB.y) << 7) + c4));
        float4 hb2 = __ldg((const float4*)(g_h0 + (((size_t)iB.z) << 7) + c4));
        float4 hb3 = __ldg((const float4*)(g_h0 + (((size_t)iB.w) << 7) + c4));

        float4 mA = make_float4(-CUDART_INF_F, -CUDART_INF_F,
                                -CUDART_INF_F, -CUDART_INF_F);
        float4 mB = mA;

        #define GMAX(m, pv, hv)                                           \
        {                                                                 \
            float4 h = hv;                                                \
            h.x = fmaxf(fmaf(h.x, sc.x, sh.x), 0.f);                      \
            h.y = fmaxf(fmaf(h.y, sc.y, sh.y), 0.f);                      \
            h.z = fmaxf(fmaf(h.z, sc.z, sh.z), 0.f);                      \
            h.w = fmaxf(fmaf(h.w, sc.w, sh.w), 0.f);                      \
            m.x = fmaxf(m.x, pv.x + h.x);                                 \
            m.y = fmaxf(m.y, pv.y + h.y);                                 \
            m.z = fmaxf(m.z, pv.z + h.z);                                 \
            m.w = fmaxf(m.w, pv.w + h.w);                                 \
        }
        GMAX(mA, pa0, ha0) GMAX(mA, pa1, ha1)
        GMAX(mA, pa2, ha2) GMAX(mA, pa3, ha3)
        GMAX(mB, pb0, hb0) GMAX(mB, pb1, hb1)
        GMAX(mB, pb2, hb2) GMAX(mB, pb3, hb3)
        #undef GMAX

        #define WRED(m)                                                    \
        m.x = fmaxf(m.x, __shfl_xor_sync(0xffffffffu, m.x, 8));            \
        m.y = fmaxf(m.y, __shfl_xor_sync(0xffffffffu, m.y, 8));            \
        m.z = fmaxf(m.z, __shfl_xor_sync(0xffffffffu, m.z, 8));            \
        m.w = fmaxf(m.w, __shfl_xor_sync(0xffffffffu, m.w, 8));            \
        m.x = fmaxf(m.x, __shfl_xor_sync(0xffffffffu, m.x, 16));           \
        m.y = fmaxf(m.y, __shfl_xor_sync(0xffffffffu, m.y, 16));           \
        m.z = fmaxf(m.z, __shfl_xor_sync(0xffffffffu, m.z, 16));           \
        m.w = fmaxf(m.w, __shfl_xor_sync(0xffffffffu, m.w, 16));
        WRED(mA)
        WRED(mB)
        #undef WRED

        if (kg == 0) {
            *(float4*)(pooled + (((size_t)n) << 7) + c4) = mA;
            lsum.x += mA.x; lsum.y += mA.y; lsum.z += mA.z; lsum.w += mA.w;
            lsq.x += mA.x * mA.x; lsq.y += mA.y * mA.y;
            lsq.z += mA.z * mA.z; lsq.w += mA.w * mA.w;
            if (v2) {
                *(float4*)(pooled + (((size_t)n2) << 7) + c4) = mB;
                lsum.x += mB.x; lsum.y += mB.y; lsum.z += mB.z; lsum.w += mB.w;
                lsq.x += mB.x * mB.x; lsq.y += mB.y * mB.y;
                lsq.z += mB.z * mB.z; lsq.w += mB.w * mB.w;
            }
        }
    }

    if (kg == 0) {
        atomicAdd(&g_sum[1][c4 + 0], lsum.x); atomicAdd(&g_sum[1][c4 + 1], lsum.y);
        atomicAdd(&g_sum[1][c4 + 2], lsum.z); atomicAdd(&g_sum[1][c4 + 3], lsum.w);
        atomicAdd(&g_sq[1][c4 + 0], lsq.x);   atomicAdd(&g_sq[1][c4 + 1], lsq.y);
        atomicAdd(&g_sq[1][c4 + 2], lsq.z);   atomicAdd(&g_sq[1][c4 + 3], lsq.w);
    }
}

// ---------------- residual epilogue (inline bn4) ------------------------------
__global__ void final_kernel(const float* __restrict__ f,
                             float* __restrict__ out,
                             const float* __restrict__ gamma,
                             const float* __restrict__ beta,
                             float invN, int N) {
    int i = (blockIdx.x * blockDim.x + threadIdx.x) * 4;
    if (i >= N * C) return;
    int c = i & (C - 1);
    float4 sc, sh;
    bn_coeff(3, c + 0, gamma, beta, invN, sc.x, sh.x);
    bn_coeff(3, c + 1, gamma, beta, invN, sc.y, sh.y);
    bn_coeff(3, c + 2, gamma, beta, invN, sc.z, sh.z);
    bn_coeff(3, c + 3, gamma, beta, invN, sc.w, sh.w);
    float4 fv = *(const float4*)(f + i);
    float4 uv = *(const float4*)(g_u + i);
    float4 o;
    o.x = fmaxf(fv.x + fmaf(uv.x, sc.x, sh.x), 0.f);
    o.y = fmaxf(fv.y + fmaf(uv.y, sc.y, sh.y), 0.f);
    o.z = fmaxf(fv.z + fmaf(uv.z, sc.z, sh.z), 0.f);
    o.w = fmaxf(fv.w + fmaf(uv.w, sc.w, sh.w), 0.f);
    *(float4*)(out + i) = o;
}

// ---------------- launcher ----------------------------------------------------
extern "C" void kernel_launch(void* const* d_in, const int* in_sizes, int n_in,
                              void* d_out, int out_size) {
    const float* f_in  = (const float*)d_in[1];
    const float* pe    = (const float*)d_in[2];
    const int*   knn   = (const int*)  d_in[3];
    const float* W_pre = (const float*)d_in[4];
    const float* b_pre = (const float*)d_in[5];
    const float* g1    = (const float*)d_in[6];
    const float* be1   = (const float*)d_in[7];
    const float* g2    = (const float*)d_in[8];
    const float* be2   = (const float*)d_in[9];
    const float* W_f1  = (const float*)d_in[10];
    const float* b_f1  = (const float*)d_in[11];
    const float* g3    = (const float*)d_in[12];
    const float* be3   = (const float*)d_in[13];
    const float* W_f2  = (const float*)d_in[14];
    const float* b_f2  = (const float*)d_in[15];
    const float* g4    = (const float*)d_in[16];
    const float* be4   = (const float*)d_in[17];
    float* out = (float*)d_out;

    const int N = in_sizes[0] / 3;
    const float invN = 1.0f / (float)N;

    float *p_h0, *p_pooled, *p_t, *p_u;
    cudaGetSymbolAddress((void**)&p_h0, g_h0);
    cudaGetSymbolAddress((void**)&p_pooled, g_pooled);
    cudaGetSymbolAddress((void**)&p_t, g_t);
    cudaGetSymbolAddress((void**)&p_u, g_u);

    const int SMEM_GEMM =
        (128 * PADW + BM * PADW + 4 * C) * (int)sizeof(float);   // ~211 KB
    cudaFuncSetAttribute(gemm_kernel<0>, cudaFuncAttributeMaxDynamicSharedMemorySize, SMEM_GEMM);
    cudaFuncSetAttribute(gemm_kernel<1>, cudaFuncAttributeMaxDynamicSharedMemorySize, SMEM_GEMM);
    cudaFuncSetAttribute(gemm_kernel<2>, cudaFuncAttributeMaxDynamicSharedMemorySize, SMEM_GEMM);

    const int gemmGrid   = (N + BM - 1) / BM;
    const int gatherGrid = 1184;
    const int finalGrid  = (N * C / 4 + 255) / 256;

    zero_stats_kernel<<<1, 128>>>();

    gemm_kernel<0><<<gemmGrid, 256, SMEM_GEMM>>>(
        f_in, W_pre, b_pre, p_h0, nullptr, nullptr, invN, 0, 0, N);

    gather_kernel<<<gatherGrid, 256>>>(pe, knn, p_pooled, g1, be1, invN, N);

    gemm_kernel<1><<<gemmGrid, 256, SMEM_GEMM>>>(
        p_pooled, W_f1, b_f1, p_t, g2, be2, invN, 1, 2, N);

    gemm_kernel<2><<<gemmGrid, 256, SMEM_GEMM>>>(
        p_t, W_f2, b_f2, p_u, g3, be3, invN, 2, 3, N);

    final_kernel<<<finalGrid, 256>>>(f_in, out, g4, be4, invN, N);
}

// round 17
// speedup vs baseline: 1.1663x; 1.1406x over previous
#include <cuda_runtime.h>
#include <cstdint>
#include <math_constants.h>

constexpr int C  = 128;
constexpr int KN = 16;
constexpr int NMAX = 100000;

// ---------------- device scratch -------------------------------------------
__device__ float g_h0[(size_t)NMAX * C];
__device__ float g_pooled[(size_t)NMAX * C];
__device__ float g_t[(size_t)NMAX * C];
__device__ float g_u[(size_t)NMAX * C];

__device__ float g_sum[4][C];
__device__ float g_sq[4][C];

// ---------------- helpers ----------------------------------------------------
__device__ __forceinline__ uint32_t f2tf32(float x) {
    uint32_t r;
    asm("cvt.rna.tf32.f32 %0, %1;" : "=r"(r) : "f"(x));
    return r;
}

__device__ __forceinline__ void mma_tf32(float* d, const uint32_t* a,
                                         uint32_t b0, uint32_t b1) {
    asm volatile(
        "mma.sync.aligned.m16n8k8.row.col.f32.tf32.tf32.f32 "
        "{%0,%1,%2,%3}, {%4,%5,%6,%7}, {%8,%9}, {%0,%1,%2,%3};"
        : "+f"(d[0]), "+f"(d[1]), "+f"(d[2]), "+f"(d[3])
        : "r"(a[0]), "r"(a[1]), "r"(a[2]), "r"(a[3]), "r"(b0), "r"(b1));
}

__device__ __forceinline__ void bn_coeff(int s, int c, const float* gamma,
                                         const float* beta, float invN,
                                         float& sc, float& sh) {
    float mean = g_sum[s][c] * invN;
    float var  = g_sq[s][c] * invN - mean * mean;
    sc = __ldg(gamma + c) * rsqrtf(var + 1e-5f);
    sh = __ldg(beta + c) - mean * sc;
}

// ---------------- tiny kernels ----------------------------------------------
__global__ void zero_stats_kernel() {
    int i = threadIdx.x;
    if (i < C) {
        #pragma unroll
        for (int s = 0; s < 4; s++) { g_sum[s][i] = 0.f; g_sq[s][i] = 0.f; }
    }
}

// stats over a [N,C] array into slot s (block-reduced, few global atomics)
__global__ void stats_kernel(const float* __restrict__ x, int s, int N) {
    __shared__ float ssum[C], ssq[C];
    const int tid = threadIdx.x;
    if (tid < C) { ssum[tid] = 0.f; ssq[tid] = 0.f; }
    __syncthreads();

    const int c4 = (tid & 31) * 4;
    const int r0 = blockIdx.x * 8 + (tid >> 5);
    const int rs = gridDim.x * 8;

    float s0 = 0.f, s1 = 0.f, s2 = 0.f, s3 = 0.f;
    float q0 = 0.f, q1 = 0.f, q2 = 0.f, q3 = 0.f;
    for (int r = r0; r < N; r += rs) {
        float4 v = __ldg((const float4*)(x + ((size_t)r << 7) + c4));
        s0 += v.x; s1 += v.y; s2 += v.z; s3 += v.w;
        q0 += v.x * v.x; q1 += v.y * v.y; q2 += v.z * v.z; q3 += v.w * v.w;
    }
    atomicAdd(&ssum[c4 + 0], s0); atomicAdd(&ssum[c4 + 1], s1);
    atomicAdd(&ssum[c4 + 2], s2); atomicAdd(&ssum[c4 + 3], s3);
    atomicAdd(&ssq[c4 + 0], q0);  atomicAdd(&ssq[c4 + 1], q1);
    atomicAdd(&ssq[c4 + 2], q2);  atomicAdd(&ssq[c4 + 3], q3);
    __syncthreads();
    if (tid < C) {
        atomicAdd(&g_sum[s][tid], ssum[tid]);
        atomicAdd(&g_sq[s][tid],  ssq[tid]);
    }
}

// ---------------- tf32 tensor-core GEMM (R11 verbatim) -----------------------
constexpr int PADW = 136;
constexpr int BM   = 256;

template <int MODE>
__global__ __launch_bounds__(256, 1)
void gemm_kernel(const float* __restrict__ A,
                 const float* __restrict__ W,
                 const float* __restrict__ bias,
                 float* __restrict__ out,
                 const float* __restrict__ gamma,
                 const float* __restrict__ beta,
                 float invN,
                 int stat_in, int stat_out, int N) {
    extern __shared__ float smem[];
    uint32_t* sW  = (uint32_t*)smem;            // [128][136] tf32 bits
    uint32_t* sA  = sW + 128 * PADW;            // [256][136] tf32 bits
    float*    sAf = (float*)sA;                 // reused for output staging
    float*    sSum   = (float*)(sA + BM * PADW);
    float*    sSq    = sSum + C;
    float*    sScale = sSq + C;
    float*    sShift = sScale + C;

    const int tid  = threadIdx.x;
    const int row0 = blockIdx.x * BM;

    if (tid < C) {
        sSum[tid] = 0.f; sSq[tid] = 0.f;
        if (MODE >= 1) {
            float sc, sh;
            bn_coeff(stat_in, tid, gamma, beta, invN, sc, sh);
            sScale[tid] = sc; sShift[tid] = sh;
        }
    }
    if (MODE >= 1) __syncthreads();

    for (int i = tid * 4; i < C * C; i += 1024) {
        int k = i >> 7, n = i & 127;
        float4 w = *(const float4*)(W + i);
        uint4 t4;
        t4.x = f2tf32(w.x); t4.y = f2tf32(w.y);
        t4.z = f2tf32(w.z); t4.w = f2tf32(w.w);
        *(uint4*)(sW + k * PADW + n) = t4;
    }
    for (int i = tid * 4; i < BM * C; i += 1024) {
        int r = i >> 7, c = i & 127;
        int row = row0 + r;
        float4 v = make_float4(0.f, 0.f, 0.f, 0.f);
        if (row < N) v = *(const float4*)(A + (size_t)row * C + c);
        if (MODE >= 1) {
            v.x = fmaf(v.x, sScale[c + 0], sShift[c + 0]);
            v.y = fmaf(v.y, sScale[c + 1], sShift[c + 1]);
            v.z = fmaf(v.z, sScale[c + 2], sShift[c + 2]);
            v.w = fmaf(v.w, sScale[c + 3], sShift[c + 3]);
            if (MODE == 2) {
                v.x = fmaxf(v.x, 0.f); v.y = fmaxf(v.y, 0.f);
                v.z = fmaxf(v.z, 0.f); v.w = fmaxf(v.w, 0.f);
            }
        }
        uint4 t4;
        t4.x = f2tf32(v.x); t4.y = f2tf32(v.y);
        t4.z = f2tf32(v.z); t4.w = f2tf32(v.w);
        *(uint4*)(sA + r * PADW + c) = t4;
    }
    __syncthreads();

    const int warp = tid >> 5, lane = tid & 31;
    const int g = lane >> 2, t = lane & 3;
    const int r0w = warp * 32;

    float d[2][16][4];
    #pragma unroll
    for (int rs = 0; rs < 2; rs++)
        #pragma unroll
        for (int nf = 0; nf < 16; nf++)
            #pragma unroll
            for (int j = 0; j < 4; j++) d[rs][nf][j] = 0.f;

    #pragma unroll 1
    for (int ks = 0; ks < 16; ks++) {
        const int k0 = ks * 8;
        uint32_t a[2][4];
        #pragma unroll
        for (int rs = 0; rs < 2; rs++) {
            const uint32_t* p = sA + (r0w + rs * 16 + g) * PADW + k0 + t;
            a[rs][0] = p[0];
            a[rs][1] = p[8 * PADW];
            a[rs][2] = p[4];
            a[rs][3] = p[8 * PADW + 4];
        }
        const uint32_t* bp = sW + (k0 + t) * PADW + g;
        #pragma unroll
        for (int nf = 0; nf < 16; nf++) {
            uint32_t b0 = bp[nf * 8];
            uint32_t b1 = bp[4 * PADW + nf * 8];
            mma_tf32(d[0][nf], a[0], b0, b1);
            mma_tf32(d[1][nf], a[1], b0, b1);
        }
    }
    __syncthreads();

    #pragma unroll
    for (int rs = 0; rs < 2; rs++) {
        #pragma unroll
        for (int nf = 0; nf < 16; nf++) {
            int row = r0w + rs * 16 + g;
            int col = nf * 8 + 2 * t;
            *(float2*)(sAf + row * PADW + col) =
                make_float2(d[rs][nf][0], d[rs][nf][1]);
            *(float2*)(sAf + (row + 8) * PADW + col) =
                make_float2(d[rs][nf][2], d[rs][nf][3]);
        }
    }
    __syncthreads();

    const int c4 = (tid * 4) & 127;
    float4 bv = *(const float4*)(bias + c4);
    float ls0 = 0.f, ls1 = 0.f, ls2 = 0.f, ls3 = 0.f;
    float lq0 = 0.f, lq1 = 0.f, lq2 = 0.f, lq3 = 0.f;
    #pragma unroll 1
    for (int it = 0; it < 32; it++) {
        int r = (tid >> 5) + it * 8;
        int row = row0 + r;
        if (row < N) {
            float4 v = *(float4*)(sAf + r * PADW + c4);
            v.x += bv.x; v.y += bv.y; v.z += bv.z; v.w += bv.w;
            *(float4*)(out + (size_t)row * C + c4) = v;
            ls0 += v.x; ls1 += v.y; ls2 += v.z; ls3 += v.w;
            lq0 += v.x * v.x; lq1 += v.y * v.y;
            lq2 += v.z * v.z; lq3 += v.w * v.w;
        }
    }
    atomicAdd(&sSum[c4 + 0], ls0); atomicAdd(&sSum[c4 + 1], ls1);
    atomicAdd(&sSum[c4 + 2], ls2); atomicAdd(&sSum[c4 + 3], ls3);
    atomicAdd(&sSq[c4 + 0], lq0);  atomicAdd(&sSq[c4 + 1], lq1);
    atomicAdd(&sSq[c4 + 2], lq2);  atomicAdd(&sSq[c4 + 3], lq3);
    __syncthreads();
    if (tid < C) {
        atomicAdd(&g_sum[stat_out][tid], sSum[tid]);
        atomicAdd(&g_sq[stat_out][tid],  sSq[tid]);
    }
}

// ---------------- gather + max-pool v8: R11 2-pt ILP, NO stats, occ=5 --------
__global__ __launch_bounds__(256, 5)
void gather_kernel(const float* __restrict__ pe,
                   const int* __restrict__ knn,
                   float* __restrict__ pooled,
                   const float* __restrict__ gamma,
                   const float* __restrict__ beta,
                   float invN, int N) {
    const int w    = (blockIdx.x * blockDim.x + threadIdx.x) >> 5;
    const int lane = threadIdx.x & 31;
    const int kg   = lane >> 3;
    const int cg   = lane & 7;
    const int c4   = (w & 3) * 32 + cg * 4;
    const int nG   = (gridDim.x * blockDim.x) >> 7;

    float4 sc, sh;
    bn_coeff(0, c4 + 0, gamma, beta, invN, sc.x, sh.x);
    bn_coeff(0, c4 + 1, gamma, beta, invN, sc.y, sh.y);
    bn_coeff(0, c4 + 2, gamma, beta, invN, sc.z, sh.z);
    bn_coeff(0, c4 + 3, gamma, beta, invN, sc.w, sh.w);

    for (int n = (w >> 2); n < N; n += 2 * nG) {
        const int  n2 = n + nG;
        const bool v2 = (n2 < N);
        const int  n2c = v2 ? n2 : n;

        int4 iA = __ldg((const int4*)(knn + (size_t)n  * KN) + kg);
        int4 iB = __ldg((const int4*)(knn + (size_t)n2c * KN) + kg);

        const float4* peA =
            (const float4*)(pe + (((size_t)n * KN + kg * 4) << 7) + c4);
        const float4* peB =
            (const float4*)(pe + (((size_t)n2c * KN + kg * 4) << 7) + c4);

        float4 pa0 = __ldcs(peA),      pa1 = __ldcs(peA + 32);
        float4 pa2 = __ldcs(peA + 64), pa3 = __ldcs(peA + 96);
        float4 pb0 = __ldcs(peB),      pb1 = __ldcs(peB + 32);
        float4 pb2 = __ldcs(peB + 64), pb3 = __ldcs(peB + 96);

        float4 ha0 = __ldg((const float4*)(g_h0 + (((size_t)iA.x) << 7) + c4));
        float4 ha1 = __ldg((const float4*)(g_h0 + (((size_t)iA.y) << 7) + c4));
        float4 ha2 = __ldg((const float4*)(g_h0 + (((size_t)iA.z) << 7) + c4));
        float4 ha3 = __ldg((const float4*)(g_h0 + (((size_t)iA.w) << 7) + c4));
        float4 hb0 = __ldg((const float4*)(g_h0 + (((size_t)iB.x) << 7) + c4));
        float4 hb1 = __ldg((const float4*)(g_h0 + (((size_t)iB.y) << 7) + c4));
        float4 hb2 = __ldg((const float4*)(g_h0 + (((size_t)iB.z) << 7) + c4));
        float4 hb3 = __ldg((const float4*)(g_h0 + (((size_t)iB.w) << 7) + c4));

        float4 mA = make_float4(-CUDART_INF_F, -CUDART_INF_F,
                                -CUDART_INF_F, -CUDART_INF_F);
        float4 mB = mA;

        #define GMAX(m, pv, hv)                                           \
        {                                                                 \
            float4 h = hv;                                                \
            h.x = fmaxf(fmaf(h.x, sc.x, sh.x), 0.f);                      \
            h.y = fmaxf(fmaf(h.y, sc.y, sh.y), 0.f);                      \
            h.z = fmaxf(fmaf(h.z, sc.z, sh.z), 0.f);                      \
            h.w = fmaxf(fmaf(h.w, sc.w, sh.w), 0.f);                      \
            m.x = fmaxf(m.x, pv.x + h.x);                                 \
            m.y = fmaxf(m.y, pv.y + h.y);                                 \
            m.z = fmaxf(m.z, pv.z + h.z);                                 \
            m.w = fmaxf(m.w, pv.w + h.w);                                 \
        }
        GMAX(mA, pa0, ha0) GMAX(mA, pa1, ha1)
        GMAX(mA, pa2, ha2) GMAX(mA, pa3, ha3)
        GMAX(mB, pb0, hb0) GMAX(mB, pb1, hb1)
        GMAX(mB, pb2, hb2) GMAX(mB, pb3, hb3)
        #undef GMAX

        #define WRED(m)                                                    \
        m.x = fmaxf(m.x, __shfl_xor_sync(0xffffffffu, m.x, 8));            \
        m.y = fmaxf(m.y, __shfl_xor_sync(0xffffffffu, m.y, 8));            \
        m.z = fmaxf(m.z, __shfl_xor_sync(0xffffffffu, m.z, 8));            \
        m.w = fmaxf(m.w, __shfl_xor_sync(0xffffffffu, m.w, 8));            \
        m.x = fmaxf(m.x, __shfl_xor_sync(0xffffffffu, m.x, 16));           \
        m.y = fmaxf(m.y, __shfl_xor_sync(0xffffffffu, m.y, 16));           \
        m.z = fmaxf(m.z, __shfl_xor_sync(0xffffffffu, m.z, 16));           \
        m.w = fmaxf(m.w, __shfl_xor_sync(0xffffffffu, m.w, 16));
        WRED(mA)
        WRED(mB)
        #undef WRED

        if (kg == 0) {
            *(float4*)(pooled + (((size_t)n) << 7) + c4) = mA;
            if (v2)
                *(float4*)(pooled + (((size_t)n2) << 7) + c4) = mB;
        }
    }
}

// ---------------- residual epilogue (R11 verbatim) ---------------------------
__global__ void final_kernel(const float* __restrict__ f,
                             float* __restrict__ out,
                             const float* __restrict__ gamma,
                             const float* __restrict__ beta,
                             float invN, int N) {
    int i = (blockIdx.x * blockDim.x + threadIdx.x) * 4;
    if (i >= N * C) return;
    int c = i & (C - 1);
    float4 sc, sh;
    bn_coeff(3, c + 0, gamma, beta, invN, sc.x, sh.x);
    bn_coeff(3, c + 1, gamma, beta, invN, sc.y, sh.y);
    bn_coeff(3, c + 2, gamma, beta, invN, sc.z, sh.z);
    bn_coeff(3, c + 3, gamma, beta, invN, sc.w, sh.w);
    float4 fv = *(const float4*)(f + i);
    float4 uv = *(const float4*)(g_u + i);
    float4 o;
    o.x = fmaxf(fv.x + fmaf(uv.x, sc.x, sh.x), 0.f);
    o.y = fmaxf(fv.y + fmaf(uv.y, sc.y, sh.y), 0.f);
    o.z = fmaxf(fv.z + fmaf(uv.z, sc.z, sh.z), 0.f);
    o.w = fmaxf(fv.w + fmaf(uv.w, sc.w, sh.w), 0.f);
    *(float4*)(out + i) = o;
}

// ---------------- launcher ----------------------------------------------------
extern "C" void kernel_launch(void* const* d_in, const int* in_sizes, int n_in,
                              void* d_out, int out_size) {
    const float* f_in  = (const float*)d_in[1];
    const float* pe    = (const float*)d_in[2];
    const int*   knn   = (const int*)  d_in[3];
    const float* W_pre = (const float*)d_in[4];
    const float* b_pre = (const float*)d_in[5];
    const float* g1    = (const float*)d_in[6];
    const float* be1   = (const float*)d_in[7];
    const float* g2    = (const float*)d_in[8];
    const float* be2   = (const float*)d_in[9];
    const float* W_f1  = (const float*)d_in[10];
    const float* b_f1  = (const float*)d_in[11];
    const float* g3    = (const float*)d_in[12];
    const float* be3   = (const float*)d_in[13];
    const float* W_f2  = (const float*)d_in[14];
    const float* b_f2  = (const float*)d_in[15];
    const float* g4    = (const float*)d_in[16];
    const float* be4   = (const float*)d_in[17];
    float* out = (float*)d_out;

    const int N = in_sizes[0] / 3;
    const float invN = 1.0f / (float)N;

    float *p_h0, *p_pooled, *p_t, *p_u;
    cudaGetSymbolAddress((void**)&p_h0, g_h0);
    cudaGetSymbolAddress((void**)&p_pooled, g_pooled);
    cudaGetSymbolAddress((void**)&p_t, g_t);
    cudaGetSymbolAddress((void**)&p_u, g_u);

    const int SMEM_GEMM =
        (128 * PADW + BM * PADW + 4 * C) * (int)sizeof(float);   // ~211 KB
    cudaFuncSetAttribute(gemm_kernel<0>, cudaFuncAttributeMaxDynamicSharedMemorySize, SMEM_GEMM);
    cudaFuncSetAttribute(gemm_kernel<1>, cudaFuncAttributeMaxDynamicSharedMemorySize, SMEM_GEMM);
    cudaFuncSetAttribute(gemm_kernel<2>, cudaFuncAttributeMaxDynamicSharedMemorySize, SMEM_GEMM);

    const int gemmGrid   = (N + BM - 1) / BM;
    const int gatherGrid = 1184;
    const int statsGrid  = 592;
    const int finalGrid  = (N * C / 4 + 255) / 256;

    zero_stats_kernel<<<1, 128>>>();

    // h0 = f @ W_pre + b_pre, stats -> slot 0
    gemm_kernel<0><<<gemmGrid, 256, SMEM_GEMM>>>(
        f_in, W_pre, b_pre, p_h0, nullptr, nullptr, invN, 0, 0, N);

    // pooled = max_k(pe + relu(bn1(h0[knn])))  (no stats in-kernel)
    gather_kernel<<<gatherGrid, 256>>>(pe, knn, p_pooled, g1, be1, invN, N);
    // stats of pooled -> slot 1
    stats_kernel<<<statsGrid, 256>>>(p_pooled, 1, N);

    // t = bn2(pooled) @ W_f1 + b_f1, stats -> slot 2
    gemm_kernel<1><<<gemmGrid, 256, SMEM_GEMM>>>(
        p_pooled, W_f1, b_f1, p_t, g2, be2, invN, 1, 2, N);

    // u = relu(bn3(t)) @ W_f2 + b_f2, stats -> slot 3
    gemm_kernel<2><<<gemmGrid, 256, SMEM_GEMM>>>(
        p_t, W_f2, b_f2, p_u, g3, be3, invN, 2, 3, N);

    // out = relu(f + bn4(u))
    final_kernel<<<finalGrid, 256>>>(f_in, out, g4, be4, invN, N);
}